// round 1
// baseline (speedup 1.0000x reference)
#include <cuda_runtime.h>
#include <cuda_bf16.h>

#define D_DIM 128
#define K_DIM 32
#define MAXN 20000

// Scratch (no allocation allowed): precomputed trans_self_feats and trans_self.
__device__ float g_tsf[MAXN * D_DIM];
__device__ float g_ts[MAXN];

__device__ __forceinline__ float sigmoidf(float x) {
    return 1.0f / (1.0f + __expf(-x));
}

// ---------------------------------------------------------------------------
// Kernel 1: g_ts[n] = self_vecs[n,:] . gate_self_w
//           g_tsf[n,:] = self_feats[n,:] @ self_weights
// 64 rows per block, 256 threads. W read via L1 (__ldg), A staged in smem.
// ---------------------------------------------------------------------------
__global__ __launch_bounds__(256)
void precompute_kernel(const float* __restrict__ self_feats,
                       const float* __restrict__ self_vecs,
                       const float* __restrict__ gate_self_w,
                       const float* __restrict__ self_weights,
                       int N) {
    __shared__ float As[64][D_DIM];
    __shared__ float gsw_s[D_DIM];

    const int tid = threadIdx.x;
    const int r0  = blockIdx.x * 64;
    const int rows = min(64, N - r0);

    if (tid < 32)
        ((float4*)gsw_s)[tid] = ((const float4*)gate_self_w)[tid];

    // Stage A rows (zero-fill tail)
    for (int i = tid; i < 64 * 32; i += 256) {
        int r = i >> 5, c = i & 31;
        float4 v = make_float4(0.f, 0.f, 0.f, 0.f);
        if (r < rows)
            v = ((const float4*)(self_feats + (size_t)(r0 + r) * D_DIM))[c];
        *(float4*)&As[r][c * 4] = v;
    }
    __syncthreads();

    // ts via warp reductions (self_vecs from gmem)
    {
        int w = tid >> 5, lane = tid & 31;
        for (int rr = w; rr < rows; rr += 8) {
            float4 v = ((const float4*)(self_vecs + (size_t)(r0 + rr) * D_DIM))[lane];
            float4 g = ((const float4*)gsw_s)[lane];
            float s = v.x * g.x + v.y * g.y + v.z * g.z + v.w * g.w;
            #pragma unroll
            for (int o = 16; o > 0; o >>= 1)
                s += __shfl_xor_sync(0xffffffffu, s, o);
            if (lane == 0) g_ts[r0 + rr] = s;
        }
    }

    // GEMM: each thread -> 8 rows x 4 cols
    const int tx = tid & 31;   // col tile: e = 4*tx .. 4*tx+3
    const int ty = tid >> 5;   // row group: rows ty*8 .. ty*8+7
    float acc[8][4];
    #pragma unroll
    for (int i = 0; i < 8; i++)
        #pragma unroll
        for (int j = 0; j < 4; j++) acc[i][j] = 0.f;

    const float4* W4 = (const float4*)self_weights;
    #pragma unroll 4
    for (int d = 0; d < D_DIM; ++d) {
        float4 wv = __ldg(&W4[d * 32 + tx]);
        #pragma unroll
        for (int i = 0; i < 8; i++) {
            float a = As[ty * 8 + i][d];
            acc[i][0] += a * wv.x;
            acc[i][1] += a * wv.y;
            acc[i][2] += a * wv.z;
            acc[i][3] += a * wv.w;
        }
    }
    #pragma unroll
    for (int i = 0; i < 8; i++) {
        int r = ty * 8 + i;
        if (r < rows) {
            float4 v = make_float4(acc[i][0], acc[i][1], acc[i][2], acc[i][3]);
            *(float4*)(g_tsf + (size_t)(r0 + r) * D_DIM + tx * 4) = v;
        }
    }
}

// ---------------------------------------------------------------------------
// Kernel 2: one block per node n. 256 threads.
//   gate[k]  = sigmoid(ts[n] + neigh[n,k].gnw + link[n,k].glw)
//   S[k,e]   = link[n,k,:] @ link_weights[:,e]      (32x128x128 GEMM)
//   out[n,e] = relu( tsf[n,e] * (1/K) * sum_k neigh[n,k,e]*sigmoid(S[k,e])
//                    * gate[k]/p[n,k] )
// ---------------------------------------------------------------------------
__global__ __launch_bounds__(256)
void main_kernel(const float* __restrict__ neigh_vecs,
                 const float* __restrict__ link_vecs,
                 const float* __restrict__ select_probs,
                 const float* __restrict__ gate_neigh_w,
                 const float* __restrict__ gate_link_w,
                 const float* __restrict__ link_weights,
                 float* __restrict__ out, int N) {
    __shared__ float Ls[K_DIM][D_DIM];   // 16 KB  link tile
    __shared__ float Ns[K_DIM][D_DIM];   // 16 KB  neigh tile
    __shared__ float red[8][D_DIM];      // 4 KB   cross-warp k-reduction
    __shared__ float tsf_s[D_DIM];
    __shared__ float gnw_s[D_DIM];
    __shared__ float glw_s[D_DIM];
    __shared__ float gdp[K_DIM];         // gate/(K*p)
    __shared__ float ps[K_DIM];
    __shared__ float tss;

    const int n   = blockIdx.x;
    const int tid = threadIdx.x;
    if (n >= N) return;

    // ---- Stage loads ----
    const float4* lk4 = (const float4*)(link_vecs  + (size_t)n * K_DIM * D_DIM);
    const float4* nb4 = (const float4*)(neigh_vecs + (size_t)n * K_DIM * D_DIM);
    #pragma unroll
    for (int i = tid; i < K_DIM * D_DIM / 4; i += 256) {
        ((float4*)Ls)[i] = lk4[i];
        ((float4*)Ns)[i] = nb4[i];
    }
    if (tid < 32) {
        ((float4*)tsf_s)[tid] = ((const float4*)(g_tsf + (size_t)n * D_DIM))[tid];
        ps[tid] = select_probs[(size_t)n * K_DIM + tid];
        ((float4*)gnw_s)[tid] = ((const float4*)gate_neigh_w)[tid];
    } else if (tid < 64) {
        ((float4*)glw_s)[tid - 32] = ((const float4*)gate_link_w)[tid - 32];
    }
    if (tid == 0) tss = g_ts[n];
    __syncthreads();

    // ---- Gate: warp w handles k = 4w..4w+3 ----
    {
        const int w = tid >> 5, lane = tid & 31;
        #pragma unroll
        for (int kk = 0; kk < 4; ++kk) {
            int k = w * 4 + kk;
            float4 lv = ((float4*)&Ls[k][0])[lane];
            float4 nv = ((float4*)&Ns[k][0])[lane];
            float4 gl = ((float4*)glw_s)[lane];
            float4 gn = ((float4*)gnw_s)[lane];
            float s = lv.x * gl.x + lv.y * gl.y + lv.z * gl.z + lv.w * gl.w
                    + nv.x * gn.x + nv.y * gn.y + nv.z * gn.z + nv.w * gn.w;
            #pragma unroll
            for (int o = 16; o > 0; o >>= 1)
                s += __shfl_xor_sync(0xffffffffu, s, o);
            if (lane == 0) {
                float g = sigmoidf(tss + s);
                gdp[k] = g / ((float)K_DIM * ps[k]);
            }
        }
    }
    __syncthreads();

    // ---- GEMM: S[k,e]; thread tile 4k x 4e ----
    const int tx = tid & 31;   // e = 4*tx..+3
    const int ty = tid >> 5;   // k = 4*ty..+3  (ty == warp id -> smem broadcast)
    float acc[4][4];
    #pragma unroll
    for (int i = 0; i < 4; i++)
        #pragma unroll
        for (int j = 0; j < 4; j++) acc[i][j] = 0.f;

    const float4* W4 = (const float4*)link_weights;
    #pragma unroll 2
    for (int d0 = 0; d0 < D_DIM; d0 += 4) {
        float la[4][4];
        #pragma unroll
        for (int i = 0; i < 4; i++)
            *(float4*)la[i] = *(const float4*)&Ls[ty * 4 + i][d0];
        #pragma unroll
        for (int dd = 0; dd < 4; ++dd) {
            float4 wv = __ldg(&W4[(d0 + dd) * 32 + tx]);
            #pragma unroll
            for (int i = 0; i < 4; i++) {
                acc[i][0] += la[i][dd] * wv.x;
                acc[i][1] += la[i][dd] * wv.y;
                acc[i][2] += la[i][dd] * wv.z;
                acc[i][3] += la[i][dd] * wv.w;
            }
        }
    }

    // ---- Epilogue: sigmoid, weight by gdp[k], neigh multiply, reduce over k ----
    float part[4] = {0.f, 0.f, 0.f, 0.f};
    #pragma unroll
    for (int i = 0; i < 4; i++) {
        int k = ty * 4 + i;
        float g = gdp[k];
        float4 nv = *(const float4*)&Ns[k][tx * 4];
        part[0] += nv.x * sigmoidf(acc[i][0]) * g;
        part[1] += nv.y * sigmoidf(acc[i][1]) * g;
        part[2] += nv.z * sigmoidf(acc[i][2]) * g;
        part[3] += nv.w * sigmoidf(acc[i][3]) * g;
    }
    *(float4*)&red[ty][tx * 4] = make_float4(part[0], part[1], part[2], part[3]);
    __syncthreads();

    if (tid < 32) {
        float4 s = make_float4(0.f, 0.f, 0.f, 0.f);
        #pragma unroll
        for (int t = 0; t < 8; t++) {
            float4 r = ((float4*)&red[t][0])[tid];
            s.x += r.x; s.y += r.y; s.z += r.z; s.w += r.w;
        }
        float4 tf = ((float4*)tsf_s)[tid];
        s.x = fmaxf(s.x * tf.x, 0.f);
        s.y = fmaxf(s.y * tf.y, 0.f);
        s.z = fmaxf(s.z * tf.z, 0.f);
        s.w = fmaxf(s.w * tf.w, 0.f);
        ((float4*)(out + (size_t)n * D_DIM))[tid] = s;
    }
}

// ---------------------------------------------------------------------------
extern "C" void kernel_launch(void* const* d_in, const int* in_sizes, int n_in,
                              void* d_out, int out_size) {
    const float* self_feats   = (const float*)d_in[0];
    const float* self_vecs    = (const float*)d_in[1];
    const float* neigh_vecs   = (const float*)d_in[2];
    const float* link_vecs    = (const float*)d_in[3];
    const float* select_probs = (const float*)d_in[4];
    const float* gate_self_w  = (const float*)d_in[5];
    const float* gate_neigh_w = (const float*)d_in[6];
    const float* gate_link_w  = (const float*)d_in[7];
    const float* self_weights = (const float*)d_in[8];
    const float* link_weights = (const float*)d_in[9];
    float* out = (float*)d_out;

    const int N = in_sizes[0] / D_DIM;

    precompute_kernel<<<(N + 63) / 64, 256>>>(self_feats, self_vecs,
                                              gate_self_w, self_weights, N);
    main_kernel<<<N, 256>>>(neigh_vecs, link_vecs, select_probs,
                            gate_neigh_w, gate_link_w, link_weights, out, N);
}

// round 3
// speedup vs baseline: 1.9077x; 1.9077x over previous
#include <cuda_runtime.h>
#include <cuda_fp16.h>
#include <cstdint>

#define D_DIM 128
#define K_DIM 32
#define MAXN  20000

// ---------------- device scratch (no allocation allowed) ----------------
__device__ float g_tsf[MAXN * D_DIM];                     // self_feats @ self_weights
__device__ float g_ts[MAXN];                              // self_vecs . gate_self_w
__device__ __align__(16) __half g_Wh[D_DIM * D_DIM];      // W^T fp16, [e][d] row-major

__device__ __forceinline__ float sigmoidf(float x) {
    return 1.0f / (1.0f + __expf(-x));
}

// fast sigmoid: 1 MUFU (tanh.approx), abs err ~3e-4
__device__ __forceinline__ float sigmoid_fast(float x) {
    float t;
    asm("tanh.approx.f32 %0, %1;" : "=f"(t) : "f"(0.5f * x));
    return fmaf(0.5f, t, 0.5f);
}

#define MMA16816(cc, a0, a1, a2, a3, b0, b1)                                  \
    asm volatile(                                                             \
        "mma.sync.aligned.m16n8k16.row.col.f32.f16.f16.f32 "                  \
        "{%0,%1,%2,%3}, {%4,%5,%6,%7}, {%8,%9}, {%0,%1,%2,%3};"               \
        : "+f"((cc)[0]), "+f"((cc)[1]), "+f"((cc)[2]), "+f"((cc)[3])          \
        : "r"(a0), "r"(a1), "r"(a2), "r"(a3), "r"(b0), "r"(b1))

// ---------------------------------------------------------------------------
// Kernel A: g_Wh[e][d] = (half)W[d][e]
// ---------------------------------------------------------------------------
__global__ __launch_bounds__(256)
void wh_kernel(const float* __restrict__ W) {
    int idx = blockIdx.x * 256 + threadIdx.x;   // 0..8191
    int e  = idx >> 6;
    int d0 = (idx & 63) << 1;
    __half2 h = __floats2half2_rn(W[(size_t)d0 * D_DIM + e],
                                  W[(size_t)(d0 + 1) * D_DIM + e]);
    *(__half2*)(g_Wh + (size_t)e * D_DIM + d0) = h;
}

// ---------------------------------------------------------------------------
// Kernel B: g_ts / g_tsf precompute (32 rows per block, 256 threads)
// ---------------------------------------------------------------------------
__global__ __launch_bounds__(256)
void precompute_kernel(const float* __restrict__ self_feats,
                       const float* __restrict__ self_vecs,
                       const float* __restrict__ gate_self_w,
                       const float* __restrict__ self_weights,
                       int N) {
    __shared__ float As[32][D_DIM];
    __shared__ float gsw_s[D_DIM];

    const int tid = threadIdx.x;
    const int r0  = blockIdx.x * 32;

    if (tid < 32)
        ((float4*)gsw_s)[tid] = ((const float4*)gate_self_w)[tid];

    for (int i = tid; i < 32 * 32; i += 256) {
        int r = i >> 5, c = i & 31;
        float4 v = make_float4(0.f, 0.f, 0.f, 0.f);
        if (r0 + r < N)
            v = ((const float4*)(self_feats + (size_t)(r0 + r) * D_DIM))[c];
        *(float4*)&As[r][c * 4] = v;
    }
    __syncthreads();

    const int w = tid >> 5, lane = tid & 31;
    for (int rr = w; rr < 32; rr += 8) {
        if (r0 + rr < N) {
            float4 v = ((const float4*)(self_vecs + (size_t)(r0 + rr) * D_DIM))[lane];
            float4 g = ((const float4*)gsw_s)[lane];
            float s = v.x * g.x + v.y * g.y + v.z * g.z + v.w * g.w;
            #pragma unroll
            for (int o = 16; o > 0; o >>= 1)
                s += __shfl_xor_sync(0xffffffffu, s, o);
            if (lane == 0) g_ts[r0 + rr] = s;
        }
    }

    const int tx = tid & 31, ty = tid >> 5;
    float acc[4][4];
    #pragma unroll
    for (int i = 0; i < 4; i++)
        #pragma unroll
        for (int j = 0; j < 4; j++) acc[i][j] = 0.f;

    const float4* W4 = (const float4*)self_weights;
    #pragma unroll 4
    for (int d = 0; d < D_DIM; ++d) {
        float4 wv = __ldg(&W4[d * 32 + tx]);
        #pragma unroll
        for (int i = 0; i < 4; i++) {
            float a = As[ty * 4 + i][d];
            acc[i][0] += a * wv.x;
            acc[i][1] += a * wv.y;
            acc[i][2] += a * wv.z;
            acc[i][3] += a * wv.w;
        }
    }
    #pragma unroll
    for (int i = 0; i < 4; i++) {
        int r = ty * 4 + i;
        if (r0 + r < N) {
            float4 v = make_float4(acc[i][0], acc[i][1], acc[i][2], acc[i][3]);
            *(float4*)(g_tsf + (size_t)(r0 + r) * D_DIM + tx * 4) = v;
        }
    }
}

// ---------------------------------------------------------------------------
// Kernel C: main kernel. One CTA = 4 nodes, 256 threads (8 warps).
//   Ls  [128 krow][136 half]  link rows, fp16 (padded: conflict-free frags)
//   Wt  [128 e   ][136 half]  W^T, fp16
//   GEMM via mma.sync m16n8k16: warp w -> krows [16w,16w+16) x all 128 e.
//   Epilogue fused in fragments; k-reduced via shfl + smem.
// ---------------------------------------------------------------------------
#define LPAD 68                        // row stride in u32 (136 halves)
#define SM_GDP  0                      // 128 f
#define SM_RED  512                    // 8*128 f
#define SM_LINK 4608                   // 34816 B
#define SM_WT   (4608 + 34816)         // 34816 B
#define SMEM_TOTAL (SM_WT + 34816)

__global__ __launch_bounds__(256)
void tc_kernel(const float* __restrict__ neigh_vecs,
               const float* __restrict__ link_vecs,
               const float* __restrict__ select_probs,
               const float* __restrict__ gate_neigh_w,
               const float* __restrict__ gate_link_w,
               float* __restrict__ out, int N) {
    extern __shared__ char smem[];
    float*    gdp_s = (float*)(smem + SM_GDP);
    float*    red   = (float*)(smem + SM_RED);
    uint32_t* Lu    = (uint32_t*)(smem + SM_LINK);
    uint32_t* Wu    = (uint32_t*)(smem + SM_WT);

    const int tid  = threadIdx.x;
    const int w    = tid >> 5;
    const int lane = tid & 31;

    // ---- Stage: gates + link fp32->fp16 into padded smem ----
    {
        const int r = tid >> 1;               // CTA row 0..127 = node*32 + k
        const int h = tid & 1;                // half-row
        const int node = r >> 5, k = r & 31;
        const size_t ng = (size_t)blockIdx.x * 4 + node;
        const bool valid = (ng < (size_t)N);

        const float4* lrow = (const float4*)(link_vecs  + ((size_t)ng * K_DIM + k) * D_DIM) + h * 16;
        const float4* nrow = (const float4*)(neigh_vecs + ((size_t)ng * K_DIM + k) * D_DIM) + h * 16;
        const float4* glw4 = (const float4*)gate_link_w  + h * 16;
        const float4* gnw4 = (const float4*)gate_neigh_w + h * 16;
        float dl = 0.f, dn = 0.f;
        if (valid) {
            #pragma unroll 4
            for (int j = 0; j < 16; ++j) {
                float4 v = lrow[j];
                float4 g = __ldg(&glw4[j]);
                dl += v.x * g.x + v.y * g.y + v.z * g.z + v.w * g.w;
                __half2 p0 = __floats2half2_rn(v.x, v.y);
                __half2 p1 = __floats2half2_rn(v.z, v.w);
                Lu[r * LPAD + h * 32 + j * 2]     = *(uint32_t*)&p0;
                Lu[r * LPAD + h * 32 + j * 2 + 1] = *(uint32_t*)&p1;

                float4 nv = nrow[j];
                float4 gn = __ldg(&gnw4[j]);
                dn += nv.x * gn.x + nv.y * gn.y + nv.z * gn.z + nv.w * gn.w;
            }
        }
        dl += __shfl_xor_sync(0xffffffffu, dl, 1);
        dn += __shfl_xor_sync(0xffffffffu, dn, 1);
        if (h == 0 && valid) {
            float ts = g_ts[ng];
            float p  = select_probs[ng * K_DIM + k];
            gdp_s[r] = sigmoidf(ts + dl + dn) / ((float)K_DIM * p);
        }
    }

    // ---- Copy W^T fp16 into padded smem ----
    {
        const uint32_t* src = (const uint32_t*)g_Wh;
        #pragma unroll
        for (int i = tid; i < 8192; i += 256) {
            int r = i >> 6, c = i & 63;
            Wu[r * LPAD + c] = src[i];
        }
    }
    __syncthreads();

    // ---- GEMM: warp w computes S[krow 16w..16w+16)[e 0..128) ----
    const int g = lane >> 2, t = lane & 3;
    const int row0 = w * 16 + g;

    float c[64];
    #pragma unroll
    for (int i = 0; i < 64; i++) c[i] = 0.f;

    const uint32_t* La = Lu + row0 * LPAD;
    const uint32_t* Lb = Lu + (row0 + 8) * LPAD;

    #pragma unroll
    for (int ks = 0; ks < 8; ++ks) {
        const int kq = ks * 8 + t;                 // u32 index within row
        uint32_t a0 = La[kq], a1 = Lb[kq], a2 = La[kq + 4], a3 = Lb[kq + 4];
        #pragma unroll
        for (int nt = 0; nt < 16; ++nt) {
            const uint32_t* We = Wu + (nt * 8 + g) * LPAD;
            uint32_t b0 = We[kq], b1 = We[kq + 4];
            MMA16816(&c[nt * 4], a0, a1, a2, a3, b0, b1);
        }
    }

    // ---- Epilogue: sigmoid * neigh * gdp, reduce k within warp ----
    const int node = w >> 1;
    const size_t ng = (size_t)blockIdx.x * 4 + node;
    if (ng < (size_t)N) {
        const int krow = row0 & 31;               // 0..7 or 16..23
        const float* nb0 = neigh_vecs + ((size_t)ng * K_DIM + krow) * D_DIM;
        const float* nb1 = nb0 + 8 * D_DIM;
        const float gd0 = gdp_s[row0];
        const float gd1 = gdp_s[row0 + 8];

        #pragma unroll
        for (int nt = 0; nt < 16; ++nt) {
            const int col = nt * 8 + 2 * t;
            float2 n0 = *(const float2*)(nb0 + col);
            float2 n1 = *(const float2*)(nb1 + col);
            float p0 = sigmoid_fast(c[nt * 4 + 0]) * n0.x * gd0
                     + sigmoid_fast(c[nt * 4 + 2]) * n1.x * gd1;
            float p1 = sigmoid_fast(c[nt * 4 + 1]) * n0.y * gd0
                     + sigmoid_fast(c[nt * 4 + 3]) * n1.y * gd1;
            #pragma unroll
            for (int o = 4; o < 32; o <<= 1) {
                p0 += __shfl_xor_sync(0xffffffffu, p0, o);
                p1 += __shfl_xor_sync(0xffffffffu, p1, o);
            }
            if (g == 0) {
                red[w * 128 + col]     = p0;
                red[w * 128 + col + 1] = p1;
            }
        }
    }
    __syncthreads();

    // ---- Final: fold warp pairs, scale by tsf, relu, store ----
    #pragma unroll
    for (int i = tid; i < 512; i += 256) {
        const int nd = i >> 7, col = i & 127;
        const size_t n2 = (size_t)blockIdx.x * 4 + nd;
        if (n2 < (size_t)N) {
            float s = red[(2 * nd) * 128 + col] + red[(2 * nd + 1) * 128 + col];
            float tsf = g_tsf[n2 * D_DIM + col];
            out[n2 * D_DIM + col] = fmaxf(s * tsf, 0.f);
        }
    }
}

// ---------------------------------------------------------------------------
extern "C" void kernel_launch(void* const* d_in, const int* in_sizes, int n_in,
                              void* d_out, int out_size) {
    const float* self_feats   = (const float*)d_in[0];
    const float* self_vecs    = (const float*)d_in[1];
    const float* neigh_vecs   = (const float*)d_in[2];
    const float* link_vecs    = (const float*)d_in[3];
    const float* select_probs = (const float*)d_in[4];
    const float* gate_self_w  = (const float*)d_in[5];
    const float* gate_neigh_w = (const float*)d_in[6];
    const float* gate_link_w  = (const float*)d_in[7];
    const float* self_weights = (const float*)d_in[8];
    const float* link_weights = (const float*)d_in[9];
    float* out = (float*)d_out;

    const int N = in_sizes[0] / D_DIM;

    static bool attr_set = false;
    if (!attr_set) {
        cudaFuncSetAttribute(tc_kernel, cudaFuncAttributeMaxDynamicSharedMemorySize,
                             SMEM_TOTAL);
        attr_set = true;
    }

    wh_kernel<<<32, 256>>>(link_weights);
    precompute_kernel<<<(N + 31) / 32, 256>>>(self_feats, self_vecs,
                                              gate_self_w, self_weights, N);
    tc_kernel<<<(N + 3) / 4, 256, SMEM_TOTAL>>>(neigh_vecs, link_vecs, select_probs,
                                                gate_neigh_w, gate_link_w, out, N);
}

// round 7
// speedup vs baseline: 2.8603x; 1.4994x over previous
#include <cuda_runtime.h>
#include <cuda_fp16.h>
#include <cstdint>

#define D_DIM 128
#define K_DIM 32
#define MAXN  20000

// ---------------- device scratch (no allocation allowed) ----------------
__device__ float g_tsf[MAXN * D_DIM];                     // self_feats @ self_weights
__device__ float g_ts[MAXN];                              // self_vecs . gate_self_w
__device__ __align__(16) __half g_Wh[D_DIM * D_DIM];      // W^T fp16, [e][d] row-major

__device__ __forceinline__ float sigmoidf(float x) {
    return 1.0f / (1.0f + __expf(-x));
}

// fast sigmoid: 1 MUFU (tanh.approx), abs err ~3e-4
__device__ __forceinline__ float sigmoid_fast(float x) {
    float t;
    asm("tanh.approx.f32 %0, %1;" : "=f"(t) : "f"(0.5f * x));
    return fmaf(0.5f, t, 0.5f);
}

#define MMA16816(cc, a0, a1, a2, a3, b0, b1)                                  \
    asm volatile(                                                             \
        "mma.sync.aligned.m16n8k16.row.col.f32.f16.f16.f32 "                  \
        "{%0,%1,%2,%3}, {%4,%5,%6,%7}, {%8,%9}, {%0,%1,%2,%3};"               \
        : "+f"((cc)[0]), "+f"((cc)[1]), "+f"((cc)[2]), "+f"((cc)[3])          \
        : "r"(a0), "r"(a1), "r"(a2), "r"(a3), "r"(b0), "r"(b1))

// ---------------------------------------------------------------------------
// Kernel A: g_Wh[e][d] = (half)W[d][e]
// ---------------------------------------------------------------------------
__global__ __launch_bounds__(256)
void wh_kernel(const float* __restrict__ W) {
    int idx = blockIdx.x * 256 + threadIdx.x;   // 0..8191
    int e  = idx >> 6;
    int d0 = (idx & 63) << 1;
    __half2 h = __floats2half2_rn(W[(size_t)d0 * D_DIM + e],
                                  W[(size_t)(d0 + 1) * D_DIM + e]);
    *(__half2*)(g_Wh + (size_t)e * D_DIM + d0) = h;
}

// ---------------------------------------------------------------------------
// Kernel B: g_ts / g_tsf precompute (32 rows per block, 256 threads)
// ---------------------------------------------------------------------------
__global__ __launch_bounds__(256)
void precompute_kernel(const float* __restrict__ self_feats,
                       const float* __restrict__ self_vecs,
                       const float* __restrict__ gate_self_w,
                       const float* __restrict__ self_weights,
                       int N) {
    __shared__ float As[32][D_DIM];
    __shared__ float gsw_s[D_DIM];

    const int tid = threadIdx.x;
    const int r0  = blockIdx.x * 32;

    if (tid < 32)
        ((float4*)gsw_s)[tid] = ((const float4*)gate_self_w)[tid];

    for (int i = tid; i < 32 * 32; i += 256) {
        int r = i >> 5, c = i & 31;
        float4 v = make_float4(0.f, 0.f, 0.f, 0.f);
        if (r0 + r < N)
            v = ((const float4*)(self_feats + (size_t)(r0 + r) * D_DIM))[c];
        *(float4*)&As[r][c * 4] = v;
    }
    __syncthreads();

    const int w = tid >> 5, lane = tid & 31;
    for (int rr = w; rr < 32; rr += 8) {
        if (r0 + rr < N) {
            float4 v = ((const float4*)(self_vecs + (size_t)(r0 + rr) * D_DIM))[lane];
            float4 g = ((const float4*)gsw_s)[lane];
            float s = v.x * g.x + v.y * g.y + v.z * g.z + v.w * g.w;
            #pragma unroll
            for (int o = 16; o > 0; o >>= 1)
                s += __shfl_xor_sync(0xffffffffu, s, o);
            if (lane == 0) g_ts[r0 + rr] = s;
        }
    }

    const int tx = tid & 31, ty = tid >> 5;
    float acc[4][4];
    #pragma unroll
    for (int i = 0; i < 4; i++)
        #pragma unroll
        for (int j = 0; j < 4; j++) acc[i][j] = 0.f;

    const float4* W4 = (const float4*)self_weights;
    #pragma unroll 4
    for (int d = 0; d < D_DIM; ++d) {
        float4 wv = __ldg(&W4[d * 32 + tx]);
        #pragma unroll
        for (int i = 0; i < 4; i++) {
            float a = As[ty * 4 + i][d];
            acc[i][0] += a * wv.x;
            acc[i][1] += a * wv.y;
            acc[i][2] += a * wv.z;
            acc[i][3] += a * wv.w;
        }
    }
    #pragma unroll
    for (int i = 0; i < 4; i++) {
        int r = ty * 4 + i;
        if (r0 + r < N) {
            float4 v = make_float4(acc[i][0], acc[i][1], acc[i][2], acc[i][3]);
            *(float4*)(g_tsf + (size_t)(r0 + r) * D_DIM + tx * 4) = v;
        }
    }
}

// ---------------------------------------------------------------------------
// Kernel C: main kernel. One CTA = 2 nodes, 256 threads (8 warps).
//   Warp tile: 32 krows (ALL K of one node) x 32 e-cols -> c[32] accumulators,
//   k-reduction fully in-warp, direct relu+store (no smem reduction pass).
//   Ls [64 krow][136 half]  link fp16 (padded, conflict-free)
//   Ns [64 krow][136 half]  neigh fp16 (epilogue reads smem, not gmem)
//   Wt [128 e  ][136 half]  W^T fp16
// ---------------------------------------------------------------------------
#define LPAD 68                        // row stride in u32 (136 halves)
#define SM_GDP  0                      // 64 f
#define SM_LINK 256                    // 64*68*4 = 17408 B
#define SM_NEI  (256 + 17408)
#define SM_WT   (256 + 2 * 17408)      // 128*68*4 = 34816 B
#define SMEM_TOTAL (SM_WT + 34816)     // 69888 B

__global__ __launch_bounds__(256)
void tc_kernel(const float* __restrict__ neigh_vecs,
               const float* __restrict__ link_vecs,
               const float* __restrict__ select_probs,
               const float* __restrict__ gate_neigh_w,
               const float* __restrict__ gate_link_w,
               float* __restrict__ out, int N) {
    extern __shared__ char smem[];
    float*    gdp_s = (float*)(smem + SM_GDP);
    uint32_t* Lu    = (uint32_t*)(smem + SM_LINK);
    uint32_t* Nu    = (uint32_t*)(smem + SM_NEI);
    uint32_t* Wu    = (uint32_t*)(smem + SM_WT);

    const int tid  = threadIdx.x;
    const int w    = tid >> 5;
    const int lane = tid & 31;

    // ---- Stage: gates + link/neigh fp32->fp16 into padded smem ----
    {
        const int r = tid >> 2;               // CTA row 0..63 = node*32 + k
        const int h = tid & 3;                // quarter-row
        const int node = r >> 5, k = r & 31;
        const size_t ng = (size_t)blockIdx.x * 2 + node;
        const bool valid = (ng < (size_t)N);

        // thread handles float4 chunks j=0..7 at float4 idx (4j+h) -> coalesced
        const float4* lrow = (const float4*)(link_vecs  + ((size_t)ng * K_DIM + k) * D_DIM);
        const float4* nrow = (const float4*)(neigh_vecs + ((size_t)ng * K_DIM + k) * D_DIM);
        const float4* glw4 = (const float4*)gate_link_w;
        const float4* gnw4 = (const float4*)gate_neigh_w;
        float dl = 0.f, dn = 0.f;
        if (valid) {
            #pragma unroll
            for (int j = 0; j < 8; ++j) {
                const int f4 = j * 4 + h;            // float4 index 0..31
                const int cu = f4 * 2;               // u32 col 0..62
                float4 v = lrow[f4];
                float4 g = __ldg(&glw4[f4]);
                dl += v.x * g.x + v.y * g.y + v.z * g.z + v.w * g.w;
                __half2 p0 = __floats2half2_rn(v.x, v.y);
                __half2 p1 = __floats2half2_rn(v.z, v.w);
                *(uint2*)&Lu[r * LPAD + cu] = make_uint2(*(uint32_t*)&p0, *(uint32_t*)&p1);

                float4 nv = nrow[f4];
                float4 gn = __ldg(&gnw4[f4]);
                dn += nv.x * gn.x + nv.y * gn.y + nv.z * gn.z + nv.w * gn.w;
                __half2 q0 = __floats2half2_rn(nv.x, nv.y);
                __half2 q1 = __floats2half2_rn(nv.z, nv.w);
                *(uint2*)&Nu[r * LPAD + cu] = make_uint2(*(uint32_t*)&q0, *(uint32_t*)&q1);
            }
        }
        dl += __shfl_xor_sync(0xffffffffu, dl, 1);
        dl += __shfl_xor_sync(0xffffffffu, dl, 2);
        dn += __shfl_xor_sync(0xffffffffu, dn, 1);
        dn += __shfl_xor_sync(0xffffffffu, dn, 2);
        if (h == 0 && valid) {
            float ts = g_ts[ng];
            float p  = select_probs[ng * K_DIM + k];
            gdp_s[r] = sigmoidf(ts + dl + dn) / ((float)K_DIM * p);
        }
    }

    // ---- Copy W^T fp16 into padded smem (uint4 per thread x8) ----
    {
        const uint4* src = (const uint4*)g_Wh;
        #pragma unroll
        for (int i = 0; i < 8; ++i) {
            const int idx = i * 256 + tid;           // 0..2047 uint4
            const int r = idx >> 4, c = (idx & 15) << 2;
            *(uint4*)&Wu[r * LPAD + c] = src[idx];
        }
    }
    __syncthreads();

    // ---- GEMM: warp w -> node (w>>2), e-cols [(w&3)*32, +32) ----
    const int g = lane >> 2, t = lane & 3;
    const int node  = w >> 2;
    const int ecol0 = (w & 3) << 5;
    const int arow0 = node << 5;

    float c[2][4][4];
    #pragma unroll
    for (int mt = 0; mt < 2; ++mt)
        #pragma unroll
        for (int nt = 0; nt < 4; ++nt)
            #pragma unroll
            for (int j = 0; j < 4; ++j) c[mt][nt][j] = 0.f;

    #pragma unroll
    for (int ks = 0; ks < 8; ++ks) {
        const int kq = ks * 8 + t;
        uint32_t b[4][2];
        #pragma unroll
        for (int nt = 0; nt < 4; ++nt) {
            const uint32_t* We = Wu + (ecol0 + nt * 8 + g) * LPAD;
            b[nt][0] = We[kq];
            b[nt][1] = We[kq + 4];
        }
        #pragma unroll
        for (int mt = 0; mt < 2; ++mt) {
            const uint32_t* La = Lu + (arow0 + mt * 16 + g) * LPAD;
            const uint32_t* Lb = La + 8 * LPAD;
            uint32_t a0 = La[kq], a1 = Lb[kq], a2 = La[kq + 4], a3 = Lb[kq + 4];
            #pragma unroll
            for (int nt = 0; nt < 4; ++nt)
                MMA16816(c[mt][nt], a0, a1, a2, a3, b[nt][0], b[nt][1]);
        }
    }

    // ---- Epilogue: sigmoid * neigh * gdp, full k-sum in-warp, store ----
    const size_t ng = (size_t)blockIdx.x * 2 + node;
    if (ng < (size_t)N) {
        float p0[4] = {0.f, 0.f, 0.f, 0.f};
        float p1[4] = {0.f, 0.f, 0.f, 0.f};
        const int cbase = (ecol0 >> 1) + t;          // u32 col in Nu

        #pragma unroll
        for (int mt = 0; mt < 2; ++mt) {
            const int r0 = arow0 + mt * 16 + g;
            const float gd0 = gdp_s[r0];
            const float gd1 = gdp_s[r0 + 8];
            const uint32_t* n0p = Nu + r0 * LPAD;
            const uint32_t* n1p = n0p + 8 * LPAD;
            #pragma unroll
            for (int nt = 0; nt < 4; ++nt) {
                uint32_t u0 = n0p[cbase + nt * 4];
                uint32_t u1 = n1p[cbase + nt * 4];
                float2 n0 = __half22float2(*(__half2*)&u0);
                float2 n1 = __half22float2(*(__half2*)&u1);
                p0[nt] += sigmoid_fast(c[mt][nt][0]) * n0.x * gd0
                        + sigmoid_fast(c[mt][nt][2]) * n1.x * gd1;
                p1[nt] += sigmoid_fast(c[mt][nt][1]) * n0.y * gd0
                        + sigmoid_fast(c[mt][nt][3]) * n1.y * gd1;
            }
        }
        #pragma unroll
        for (int nt = 0; nt < 4; ++nt) {
            #pragma unroll
            for (int o = 4; o < 32; o <<= 1) {
                p0[nt] += __shfl_xor_sync(0xffffffffu, p0[nt], o);
                p1[nt] += __shfl_xor_sync(0xffffffffu, p1[nt], o);
            }
        }
        if (g == 0) {
            #pragma unroll
            for (int nt = 0; nt < 4; ++nt) {
                const int col = ecol0 + nt * 8 + 2 * t;
                float2 tf = *(const float2*)(g_tsf + ng * D_DIM + col);
                float2 o2;
                o2.x = fmaxf(p0[nt] * tf.x, 0.f);
                o2.y = fmaxf(p1[nt] * tf.y, 0.f);
                *(float2*)(out + ng * D_DIM + col) = o2;
            }
        }
    }
}

// ---------------------------------------------------------------------------
extern "C" void kernel_launch(void* const* d_in, const int* in_sizes, int n_in,
                              void* d_out, int out_size) {
    const float* self_feats   = (const float*)d_in[0];
    const float* self_vecs    = (const float*)d_in[1];
    const float* neigh_vecs   = (const float*)d_in[2];
    const float* link_vecs    = (const float*)d_in[3];
    const float* select_probs = (const float*)d_in[4];
    const float* gate_self_w  = (const float*)d_in[5];
    const float* gate_neigh_w = (const float*)d_in[6];
    const float* gate_link_w  = (const float*)d_in[7];
    const float* self_weights = (const float*)d_in[8];
    const float* link_weights = (const float*)d_in[9];
    float* out = (float*)d_out;

    const int N = in_sizes[0] / D_DIM;

    static bool attr_set = false;
    if (!attr_set) {
        cudaFuncSetAttribute(tc_kernel, cudaFuncAttributeMaxDynamicSharedMemorySize,
                             SMEM_TOTAL);
        attr_set = true;
    }

    wh_kernel<<<32, 256>>>(link_weights);
    precompute_kernel<<<(N + 31) / 32, 256>>>(self_feats, self_vecs,
                                              gate_self_w, self_weights, N);
    tc_kernel<<<(N + 1) / 2, 256, SMEM_TOTAL>>>(neigh_vecs, link_vecs, select_probs,
                                                gate_neigh_w, gate_link_w, out, N);
}

// round 11
// speedup vs baseline: 3.0139x; 1.0537x over previous
#include <cuda_runtime.h>
#include <cuda_fp16.h>
#include <cstdint>

#define D_DIM 128
#define K_DIM 32
#define MAXN  20000

// ---------------- device scratch (no allocation allowed) ----------------
__device__ float g_tsf[MAXN * D_DIM];                     // self_feats @ self_weights
__device__ float g_ts[MAXN];                              // self_vecs . gate_self_w
__device__ __align__(16) __half g_Wh[D_DIM * D_DIM];      // W^T fp16, [e][d] row-major

__device__ __forceinline__ float sigmoidf(float x) {
    return 1.0f / (1.0f + __expf(-x));
}

// fast sigmoid: 1 MUFU (tanh.approx), abs err ~3e-4
__device__ __forceinline__ float sigmoid_fast(float x) {
    float t;
    asm("tanh.approx.f32 %0, %1;" : "=f"(t) : "f"(0.5f * x));
    return fmaf(0.5f, t, 0.5f);
}

__device__ __forceinline__ uint32_t smem_u32(const void* p) {
    uint32_t a;
    asm("{ .reg .u64 t; cvta.to.shared.u64 t, %1; cvt.u32.u64 %0, t; }" : "=r"(a) : "l"(p));
    return a;
}

#define MMA16816(cc, a0, a1, a2, a3, b0, b1)                                  \
    asm volatile(                                                             \
        "mma.sync.aligned.m16n8k16.row.col.f32.f16.f16.f32 "                  \
        "{%0,%1,%2,%3}, {%4,%5,%6,%7}, {%8,%9}, {%0,%1,%2,%3};"               \
        : "+f"((cc)[0]), "+f"((cc)[1]), "+f"((cc)[2]), "+f"((cc)[3])          \
        : "r"(a0), "r"(a1), "r"(a2), "r"(a3), "r"(b0), "r"(b1))

#define LDSM_X4(r, a)                                                         \
    asm volatile("ldmatrix.sync.aligned.m8n8.x4.shared.b16 {%0,%1,%2,%3}, [%4];" \
        : "=r"((r)[0]), "=r"((r)[1]), "=r"((r)[2]), "=r"((r)[3]) : "r"(a))

#define CP_ASYNC16(dst, src)                                                  \
    asm volatile("cp.async.ca.shared.global [%0], [%1], 16;" :: "r"(dst), "l"(src) : "memory")

// ---------------------------------------------------------------------------
// Kernel B: g_ts / g_tsf precompute (32 rows per block, 256 threads).
// Blocks 0..31 additionally transpose link_weights -> g_Wh (fused wh_kernel).
// ---------------------------------------------------------------------------
__global__ __launch_bounds__(256)
void precompute_kernel(const float* __restrict__ self_feats,
                       const float* __restrict__ self_vecs,
                       const float* __restrict__ gate_self_w,
                       const float* __restrict__ self_weights,
                       const float* __restrict__ link_weights,
                       int N) {
    __shared__ float As[32][D_DIM];
    __shared__ float gsw_s[D_DIM];

    const int tid = threadIdx.x;
    const int r0  = blockIdx.x * 32;

    // fused W^T fp16 conversion (first 32 blocks)
    if (blockIdx.x < 32) {
        int idx = blockIdx.x * 256 + tid;           // 0..8191
        int e  = idx >> 6;
        int d0 = (idx & 63) << 1;
        __half2 h = __floats2half2_rn(link_weights[(size_t)d0 * D_DIM + e],
                                      link_weights[(size_t)(d0 + 1) * D_DIM + e]);
        *(__half2*)(g_Wh + (size_t)e * D_DIM + d0) = h;
    }

    if (tid < 32)
        ((float4*)gsw_s)[tid] = ((const float4*)gate_self_w)[tid];

    for (int i = tid; i < 32 * 32; i += 256) {
        int r = i >> 5, c = i & 31;
        float4 v = make_float4(0.f, 0.f, 0.f, 0.f);
        if (r0 + r < N)
            v = ((const float4*)(self_feats + (size_t)(r0 + r) * D_DIM))[c];
        *(float4*)&As[r][c * 4] = v;
    }
    __syncthreads();

    const int w = tid >> 5, lane = tid & 31;
    for (int rr = w; rr < 32; rr += 8) {
        if (r0 + rr < N) {
            float4 v = ((const float4*)(self_vecs + (size_t)(r0 + rr) * D_DIM))[lane];
            float4 g = ((const float4*)gsw_s)[lane];
            float s = v.x * g.x + v.y * g.y + v.z * g.z + v.w * g.w;
            #pragma unroll
            for (int o = 16; o > 0; o >>= 1)
                s += __shfl_xor_sync(0xffffffffu, s, o);
            if (lane == 0) g_ts[r0 + rr] = s;
        }
    }

    const int tx = tid & 31, ty = tid >> 5;
    float acc[4][4];
    #pragma unroll
    for (int i = 0; i < 4; i++)
        #pragma unroll
        for (int j = 0; j < 4; j++) acc[i][j] = 0.f;

    const float4* W4 = (const float4*)self_weights;
    #pragma unroll 4
    for (int d = 0; d < D_DIM; ++d) {
        float4 wv = __ldg(&W4[d * 32 + tx]);
        #pragma unroll
        for (int i = 0; i < 4; i++) {
            float a = As[ty * 4 + i][d];
            acc[i][0] += a * wv.x;
            acc[i][1] += a * wv.y;
            acc[i][2] += a * wv.z;
            acc[i][3] += a * wv.w;
        }
    }
    #pragma unroll
    for (int i = 0; i < 4; i++) {
        int r = ty * 4 + i;
        if (r0 + r < N) {
            float4 v = make_float4(acc[i][0], acc[i][1], acc[i][2], acc[i][3]);
            *(float4*)(g_tsf + (size_t)(r0 + r) * D_DIM + tx * 4) = v;
        }
    }
}

// ---------------------------------------------------------------------------
// Kernel C: main kernel. One CTA = 2 nodes, 256 threads (8 warps).
//   Warp tile: 32 krows (ALL K of one node) x 32 e-cols, ldmatrix fragment
//   loads everywhere, cp.async W copy, k-reduction fully in-warp.
//   Ls [64 krow][136 half]  link fp16
//   Ns [64 krow][136 half]  neigh fp16
//   Wt [128 e  ][136 half]  W^T fp16
// ---------------------------------------------------------------------------
#define LPAD 68                        // row stride in u32 (136 halves, 272 B)
#define RSTB 272                       // row stride bytes
#define SM_GDP  0                      // 64 f
#define SM_LINK 256                    // 17408 B
#define SM_NEI  (256 + 17408)
#define SM_WT   (256 + 2 * 17408)      // 34816 B
#define SMEM_TOTAL (SM_WT + 34816)     // 69888 B

__global__ __launch_bounds__(256, 3)
void tc_kernel(const float* __restrict__ neigh_vecs,
               const float* __restrict__ link_vecs,
               const float* __restrict__ select_probs,
               const float* __restrict__ gate_neigh_w,
               const float* __restrict__ gate_link_w,
               float* __restrict__ out, int N) {
    extern __shared__ char smem[];
    const uint32_t smem_base = smem_u32(smem);
    float*    gdp_s = (float*)(smem + SM_GDP);
    uint32_t* Lu    = (uint32_t*)(smem + SM_LINK);
    uint32_t* Nu    = (uint32_t*)(smem + SM_NEI);

    const int tid  = threadIdx.x;
    const int w    = tid >> 5;
    const int lane = tid & 31;

    // ---- W^T copy via cp.async (overlaps with stage LDGs below) ----
    {
        const uint4* src = (const uint4*)g_Wh;
        #pragma unroll
        for (int i = 0; i < 8; ++i) {
            const int idx = i * 256 + tid;           // 0..2047 uint4
            const int r = idx >> 4, cb = (idx & 15) << 4;   // bytes within row
            uint32_t dst = smem_base + SM_WT + r * RSTB + cb;
            CP_ASYNC16(dst, src + idx);
        }
        asm volatile("cp.async.commit_group;" ::: "memory");
    }

    // ---- Stage: gates + link/neigh fp32->fp16 into padded smem ----
    {
        const int r = tid >> 2;               // CTA row 0..63 = node*32 + k
        const int h = tid & 3;                // quarter-row
        const int node = r >> 5, k = r & 31;
        const size_t ng = (size_t)blockIdx.x * 2 + node;
        const bool valid = (ng < (size_t)N);

        const float4* lrow = (const float4*)(link_vecs  + ((size_t)ng * K_DIM + k) * D_DIM);
        const float4* nrow = (const float4*)(neigh_vecs + ((size_t)ng * K_DIM + k) * D_DIM);
        const float4* glw4 = (const float4*)gate_link_w;
        const float4* gnw4 = (const float4*)gate_neigh_w;
        float dl = 0.f, dn = 0.f;
        if (valid) {
            #pragma unroll
            for (int j = 0; j < 8; ++j) {
                const int f4 = j * 4 + h;            // float4 index 0..31
                const int cu = f4 * 2;               // u32 col 0..62
                float4 v = lrow[f4];
                float4 g = __ldg(&glw4[f4]);
                dl += v.x * g.x + v.y * g.y + v.z * g.z + v.w * g.w;
                __half2 p0 = __floats2half2_rn(v.x, v.y);
                __half2 p1 = __floats2half2_rn(v.z, v.w);
                *(uint2*)&Lu[r * LPAD + cu] = make_uint2(*(uint32_t*)&p0, *(uint32_t*)&p1);

                float4 nv = nrow[f4];
                float4 gn = __ldg(&gnw4[f4]);
                dn += nv.x * gn.x + nv.y * gn.y + nv.z * gn.z + nv.w * gn.w;
                __half2 q0 = __floats2half2_rn(nv.x, nv.y);
                __half2 q1 = __floats2half2_rn(nv.z, nv.w);
                *(uint2*)&Nu[r * LPAD + cu] = make_uint2(*(uint32_t*)&q0, *(uint32_t*)&q1);
            }
        }
        dl += __shfl_xor_sync(0xffffffffu, dl, 1);
        dl += __shfl_xor_sync(0xffffffffu, dl, 2);
        dn += __shfl_xor_sync(0xffffffffu, dn, 1);
        dn += __shfl_xor_sync(0xffffffffu, dn, 2);
        if (h == 0 && valid) {
            float ts = g_ts[ng];
            float p  = select_probs[ng * K_DIM + k];
            gdp_s[r] = sigmoidf(ts + dl + dn) / ((float)K_DIM * p);
        }
    }

    asm volatile("cp.async.wait_group 0;" ::: "memory");
    __syncthreads();

    // ---- GEMM: warp w -> node (w>>2), e-cols [(w&3)*32, +32) ----
    const int node  = w >> 2;
    const int ecol0 = (w & 3) << 5;
    const int arow0 = node << 5;
    const int lane15 = lane & 15;
    const int sel16  = (lane >> 4) << 4;     // +16B for k-high matrices

    // ldmatrix lane base addresses
    const uint32_t aAddr0 = smem_base + SM_LINK + (arow0 + lane15) * RSTB + sel16;
    const uint32_t aAddr1 = aAddr0 + 16 * RSTB;
    const uint32_t bAddr0 = smem_base + SM_WT + (ecol0 + lane15) * RSTB + sel16;
    const uint32_t bAddr1 = bAddr0 + 16 * RSTB;

    float c[2][4][4];
    #pragma unroll
    for (int mt = 0; mt < 2; ++mt)
        #pragma unroll
        for (int nt = 0; nt < 4; ++nt)
            #pragma unroll
            for (int j = 0; j < 4; ++j) c[mt][nt][j] = 0.f;

    #pragma unroll
    for (int ks = 0; ks < 8; ++ks) {
        const uint32_t koff = ks * 32;       // 16 halves per k-step
        uint32_t a0[4], a1[4], b0[4], b1[4];
        LDSM_X4(a0, aAddr0 + koff);          // rows arow0..+15
        LDSM_X4(a1, aAddr1 + koff);          // rows arow0+16..+31
        LDSM_X4(b0, bAddr0 + koff);          // {nt0 klo, nt1 klo, nt0 khi, nt1 khi}
        LDSM_X4(b1, bAddr1 + koff);          // nt2, nt3
        MMA16816(c[0][0], a0[0], a0[1], a0[2], a0[3], b0[0], b0[2]);
        MMA16816(c[0][1], a0[0], a0[1], a0[2], a0[3], b0[1], b0[3]);
        MMA16816(c[0][2], a0[0], a0[1], a0[2], a0[3], b1[0], b1[2]);
        MMA16816(c[0][3], a0[0], a0[1], a0[2], a0[3], b1[1], b1[3]);
        MMA16816(c[1][0], a1[0], a1[1], a1[2], a1[3], b0[0], b0[2]);
        MMA16816(c[1][1], a1[0], a1[1], a1[2], a1[3], b0[1], b0[3]);
        MMA16816(c[1][2], a1[0], a1[1], a1[2], a1[3], b1[0], b1[2]);
        MMA16816(c[1][3], a1[0], a1[1], a1[2], a1[3], b1[1], b1[3]);
    }

    // ---- Epilogue: sigmoid * neigh * gdp, full k-sum in-warp, store ----
    const size_t ng = (size_t)blockIdx.x * 2 + node;
    if (ng < (size_t)N) {
        const int g = lane >> 2, t = lane & 3;
        float p0[4] = {0.f, 0.f, 0.f, 0.f};
        float p1[4] = {0.f, 0.f, 0.f, 0.f};

        const uint32_t nAddr = smem_base + SM_NEI + (arow0 + lane15) * RSTB
                             + ecol0 * 2 + sel16;

        #pragma unroll
        for (int mt = 0; mt < 2; ++mt) {
            const int r0 = arow0 + mt * 16 + g;
            const float gd0 = gdp_s[r0];
            const float gd1 = gdp_s[r0 + 8];
            uint32_t nA[4], nB[4];
            LDSM_X4(nA, nAddr + mt * 16 * RSTB);        // nt0: {u0,u1}, nt1: {u0,u1}
            LDSM_X4(nB, nAddr + mt * 16 * RSTB + 32);   // nt2, nt3
            #pragma unroll
            for (int nt = 0; nt < 4; ++nt) {
                uint32_t u0 = (nt < 2) ? nA[nt * 2]     : nB[(nt - 2) * 2];
                uint32_t u1 = (nt < 2) ? nA[nt * 2 + 1] : nB[(nt - 2) * 2 + 1];
                float2 n0 = __half22float2(*(__half2*)&u0);
                float2 n1 = __half22float2(*(__half2*)&u1);
                p0[nt] += sigmoid_fast(c[mt][nt][0]) * n0.x * gd0
                        + sigmoid_fast(c[mt][nt][2]) * n1.x * gd1;
                p1[nt] += sigmoid_fast(c[mt][nt][1]) * n0.y * gd0
                        + sigmoid_fast(c[mt][nt][3]) * n1.y * gd1;
            }
        }
        #pragma unroll
        for (int nt = 0; nt < 4; ++nt) {
            #pragma unroll
            for (int o = 4; o < 32; o <<= 1) {
                p0[nt] += __shfl_xor_sync(0xffffffffu, p0[nt], o);
                p1[nt] += __shfl_xor_sync(0xffffffffu, p1[nt], o);
            }
        }
        if (g == 0) {
            #pragma unroll
            for (int nt = 0; nt < 4; ++nt) {
                const int col = ecol0 + nt * 8 + 2 * t;
                float2 tf = *(const float2*)(g_tsf + ng * D_DIM + col);
                float2 o2;
                o2.x = fmaxf(p0[nt] * tf.x, 0.f);
                o2.y = fmaxf(p1[nt] * tf.y, 0.f);
                *(float2*)(out + ng * D_DIM + col) = o2;
            }
        }
    }
}

// ---------------------------------------------------------------------------
extern "C" void kernel_launch(void* const* d_in, const int* in_sizes, int n_in,
                              void* d_out, int out_size) {
    const float* self_feats   = (const float*)d_in[0];
    const float* self_vecs    = (const float*)d_in[1];
    const float* neigh_vecs   = (const float*)d_in[2];
    const float* link_vecs    = (const float*)d_in[3];
    const float* select_probs = (const float*)d_in[4];
    const float* gate_self_w  = (const float*)d_in[5];
    const float* gate_neigh_w = (const float*)d_in[6];
    const float* gate_link_w  = (const float*)d_in[7];
    const float* self_weights = (const float*)d_in[8];
    const float* link_weights = (const float*)d_in[9];
    float* out = (float*)d_out;

    const int N = in_sizes[0] / D_DIM;

    static bool attr_set = false;
    if (!attr_set) {
        cudaFuncSetAttribute(tc_kernel, cudaFuncAttributeMaxDynamicSharedMemorySize,
                             SMEM_TOTAL);
        attr_set = true;
    }

    int pre_grid = (N + 31) / 32;
    if (pre_grid < 32) pre_grid = 32;
    precompute_kernel<<<pre_grid, 256>>>(self_feats, self_vecs, gate_self_w,
                                         self_weights, link_weights, N);
    tc_kernel<<<(N + 1) / 2, 256, SMEM_TOTAL>>>(neigh_vecs, link_vecs, select_probs,
                                                gate_neigh_w, gate_link_w, out, N);
}